// round 4
// baseline (speedup 1.0000x reference)
#include <cuda_runtime.h>

#define N_NODES 50000
#define N_EDGES 800000
#define IN_C    128
#define HID_C   64
#define OUT_C   64

// ---------------- scratch (static device globals; no allocations) ----------
__device__ int   g_is64;
__device__ int   g_src[N_EDGES];
__device__ int   g_dst[N_EDGES];
__device__ int   g_cnt[N_NODES];
__device__ int   g_fill[N_NODES];
__device__ int   g_rowptr[N_NODES + 1];
__device__ int   g_col[N_EDGES];
__device__ __align__(16) float g_dinv[N_NODES];
__device__ __align__(16) float g_hs1[N_NODES * HID_C];
__device__ __align__(16) float g_z1[N_NODES * HID_C];
__device__ __align__(16) float g_hs2[N_NODES * OUT_C];

// ---------------- dtype detection + normalization -------------------------
// If edge_index is int64: node ids < 50000 < 2^31, so (little-endian) every
// odd 32-bit word of the buffer is 0. If int32: odd words are real node ids,
// and 128 consecutive zeros is statistically impossible (p ~ (2e-5)^128).
__global__ void k_detect(const int* __restrict__ raw) {
    __shared__ int nz;
    int t = threadIdx.x;              // 128 threads
    if (t == 0) nz = 0;
    __syncthreads();
    if (raw[2 * t + 1] != 0) atomicAdd(&nz, 1);
    __syncthreads();
    if (t == 0) g_is64 = (nz == 0) ? 1 : 0;
}

__global__ void k_convert(const void* __restrict__ ei) {
    int i = blockIdx.x * blockDim.x + threadIdx.x;
    if (i >= N_EDGES) return;
    int s, d;
    if (g_is64) {
        const long long* e = (const long long*)ei;
        s = (int)e[i];
        d = (int)e[N_EDGES + i];
    } else {
        const int* e = (const int*)ei;
        s = e[i];
        d = e[N_EDGES + i];
    }
    if ((unsigned)s >= N_NODES) s = 0;   // defensive: never allow wild gather
    if ((unsigned)d >= N_NODES) d = 0;
    g_src[i] = s;
    g_dst[i] = d;
}

// ---------------- setup kernels -------------------------------------------
__global__ void k_init_counts() {
    int i = blockIdx.x * blockDim.x + threadIdx.x;
    if (i < N_NODES) { g_cnt[i] = 0; g_fill[i] = 0; }
}

__global__ void k_count() {
    int i = blockIdx.x * blockDim.x + threadIdx.x;
    if (i < N_EDGES) atomicAdd(&g_cnt[g_dst[i]], 1);
}

// single-block inclusive scan of g_cnt -> g_rowptr[1..N], also dinv
__global__ void k_scan() {
    __shared__ int s[1024];
    __shared__ int carry_sh;
    int tid = threadIdx.x;
    if (tid == 0) carry_sh = 0;
    __syncthreads();
    for (int base = 0; base < N_NODES; base += 1024) {
        int idx = base + tid;
        int v = (idx < N_NODES) ? g_cnt[idx] : 0;
        s[tid] = v;
        __syncthreads();
        for (int off = 1; off < 1024; off <<= 1) {
            int t = (tid >= off) ? s[tid - off] : 0;
            __syncthreads();
            s[tid] += t;
            __syncthreads();
        }
        int carry = carry_sh;
        if (idx < N_NODES) {
            g_rowptr[idx + 1] = carry + s[tid];
            g_dinv[idx] = rsqrtf((float)(v + 1));  // +1 self loop
        }
        __syncthreads();
        if (tid == 1023) carry_sh = carry + s[1023];
        __syncthreads();
    }
    if (tid == 0) g_rowptr[0] = 0;
}

__global__ void k_fill_csr() {
    int i = blockIdx.x * blockDim.x + threadIdx.x;
    if (i < N_EDGES) {
        int d = g_dst[i];
        int pos = g_rowptr[d] + atomicAdd(&g_fill[d], 1);
        if ((unsigned)pos < N_EDGES) g_col[pos] = g_src[i];
    }
}

// ---------------- GEMM: scratch[r][c] = dinv[r] * sum_k A[r][k] W[k][c] ----
// SRC_Z1: false -> A = Ain (harness input x), true -> A = g_z1
// DST:    0 -> g_hs1, 1 -> g_hs2
template <int K, bool SRC_Z1, int DST>
__global__ void k_gemm_scale(const float* __restrict__ Ain,
                             const float* __restrict__ W) {
    const float* A  = SRC_Z1 ? (const float*)g_z1 : Ain;
    float*      out = (DST == 0) ? g_hs1 : g_hs2;

    __shared__ float As[64 * 68];   // padded stride 68: conflict-free
    __shared__ float Ws[64 * 64];

    const int row0 = blockIdx.x * 64;
    const int tid  = threadIdx.x;
    const int tx   = tid & 15;      // col group
    const int ty   = tid >> 4;      // row group

    float acc[4][4];
    #pragma unroll
    for (int i = 0; i < 4; i++)
        #pragma unroll
        for (int j = 0; j < 4; j++) acc[i][j] = 0.0f;

    for (int kc = 0; kc < K; kc += 64) {
        if (kc) __syncthreads();
        {
            const float4* Wg = (const float4*)(W + kc * 64);
            for (int j = tid; j < 64 * 64 / 4; j += 256)
                ((float4*)Ws)[j] = Wg[j];
        }
        for (int j = tid; j < 64 * 64 / 4; j += 256) {
            int r  = j >> 4;            // 0..63
            int k4 = (j & 15) << 2;     // 0..60
            float4 v = make_float4(0.f, 0.f, 0.f, 0.f);
            int row = row0 + r;
            if (row < N_NODES)
                v = *(const float4*)(A + (size_t)row * K + kc + k4);
            *(float4*)(&As[r * 68 + k4]) = v;
        }
        __syncthreads();

        #pragma unroll 16
        for (int k = 0; k < 64; k++) {
            float a0 = As[(ty * 4 + 0) * 68 + k];
            float a1 = As[(ty * 4 + 1) * 68 + k];
            float a2 = As[(ty * 4 + 2) * 68 + k];
            float a3 = As[(ty * 4 + 3) * 68 + k];
            float4 b = *(const float4*)(&Ws[k * 64 + tx * 4]);
            acc[0][0] += a0 * b.x; acc[0][1] += a0 * b.y; acc[0][2] += a0 * b.z; acc[0][3] += a0 * b.w;
            acc[1][0] += a1 * b.x; acc[1][1] += a1 * b.y; acc[1][2] += a1 * b.z; acc[1][3] += a1 * b.w;
            acc[2][0] += a2 * b.x; acc[2][1] += a2 * b.y; acc[2][2] += a2 * b.z; acc[2][3] += a2 * b.w;
            acc[3][0] += a3 * b.x; acc[3][1] += a3 * b.y; acc[3][2] += a3 * b.z; acc[3][3] += a3 * b.w;
        }
    }

    #pragma unroll
    for (int i = 0; i < 4; i++) {
        int row = row0 + ty * 4 + i;
        if (row < N_NODES) {
            float dv = g_dinv[row];
            float4 o = make_float4(acc[i][0] * dv, acc[i][1] * dv,
                                   acc[i][2] * dv, acc[i][3] * dv);
            *(float4*)(out + (size_t)row * 64 + tx * 4) = o;
        }
    }
}

// ---------------- aggregation: one warp per destination node --------------
// out[d] = dinv[d] * (hs[d] + sum_{e: dst=d} hs[col[e]]) + b  (+ReLU)
template <bool LAYER2>
__global__ void k_aggregate(const float* __restrict__ bias,
                            float* __restrict__ outp) {
    int gw   = (blockIdx.x * blockDim.x + threadIdx.x) >> 5;
    int lane = threadIdx.x & 31;
    if (gw >= N_NODES) return;

    const float2* h2 = (const float2*)(LAYER2 ? g_hs2 : g_hs1);
    float2*       o2 = LAYER2 ? (float2*)outp : (float2*)g_z1;

    float2 acc = h2[(size_t)gw * 32 + lane];   // self loop term

    int e   = g_rowptr[gw];
    int end = g_rowptr[gw + 1];

    for (; e + 3 < end; e += 4) {
        int s0 = g_col[e + 0];
        int s1 = g_col[e + 1];
        int s2 = g_col[e + 2];
        int s3 = g_col[e + 3];
        float2 v0 = h2[(size_t)s0 * 32 + lane];
        float2 v1 = h2[(size_t)s1 * 32 + lane];
        float2 v2 = h2[(size_t)s2 * 32 + lane];
        float2 v3 = h2[(size_t)s3 * 32 + lane];
        acc.x += v0.x + v1.x + v2.x + v3.x;
        acc.y += v0.y + v1.y + v2.y + v3.y;
    }
    for (; e < end; e++) {
        int s = g_col[e];
        float2 v = h2[(size_t)s * 32 + lane];
        acc.x += v.x; acc.y += v.y;
    }

    float  dv = g_dinv[gw];
    float2 bb = ((const float2*)bias)[lane];
    float ox = fmaf(acc.x, dv, bb.x);
    float oy = fmaf(acc.y, dv, bb.y);
    if (!LAYER2) { ox = fmaxf(ox, 0.0f); oy = fmaxf(oy, 0.0f); }  // ReLU after layer 1
    o2[(size_t)gw * 32 + lane] = make_float2(ox, oy);
}

// ---------------- launch ---------------------------------------------------
extern "C" void kernel_launch(void* const* d_in, const int* in_sizes, int n_in,
                              void* d_out, int out_size) {
    const float* x  = (const float*)d_in[0];
    const void*  ei = d_in[1];                 // int32 OR int64 [2, 800000]
    const float* W1 = (const float*)d_in[2];
    const float* b1 = (const float*)d_in[3];
    const float* W2 = (const float*)d_in[4];
    const float* b2 = (const float*)d_in[5];
    float*      out = (float*)d_out;

    const int TB = 256;
    const int nodeBlocks = (N_NODES + TB - 1) / TB;      // 196
    const int edgeBlocks = (N_EDGES + TB - 1) / TB;      // 3125
    const int gemmBlocks = (N_NODES + 63) / 64;          // 782
    const int aggBlocks  = (N_NODES * 32 + TB - 1) / TB; // 6250

    k_detect<<<1, 128>>>((const int*)ei);
    k_convert<<<edgeBlocks, TB>>>(ei);
    k_init_counts<<<nodeBlocks, TB>>>();
    k_count<<<edgeBlocks, TB>>>();
    k_scan<<<1, 1024>>>();
    k_fill_csr<<<edgeBlocks, TB>>>();

    // layer 1: h = (x @ W1) * dinv -> aggregate (+bias, ReLU) -> g_z1
    k_gemm_scale<IN_C, false, 0><<<gemmBlocks, TB>>>(x, W1);
    k_aggregate<false><<<aggBlocks, TB>>>(b1, nullptr);

    // layer 2: h = (g_z1 @ W2) * dinv -> aggregate (+bias) -> out
    k_gemm_scale<HID_C, true, 1><<<gemmBlocks, TB>>>(nullptr, W2);
    k_aggregate<true><<<aggBlocks, TB>>>(b2, out);
}

// round 5
// speedup vs baseline: 1.6629x; 1.6629x over previous
#include <cuda_runtime.h>

#define N_NODES 50000
#define N_EDGES 800000
#define IN_C    128
#define HID_C   64
#define OUT_C   64
#define NODE_BLKS 196   // ceil(50000/256)

// ---------------- scratch (static device globals; no allocations) ----------
__device__ int   g_is64;
__device__ int   g_src[N_EDGES];
__device__ int   g_dst[N_EDGES];
__device__ int   g_cnt[N_NODES];
__device__ int   g_bsum[NODE_BLKS];
__device__ int   g_boff[NODE_BLKS];
__device__ int   g_rowptr[N_NODES + 1];
__device__ int   g_col[N_EDGES];
__device__ __align__(16) float g_dinv[N_NODES];
__device__ __align__(16) float g_hs1[N_NODES * HID_C];
__device__ __align__(16) float g_z1[N_NODES * HID_C];
__device__ __align__(16) float g_hs2[N_NODES * OUT_C];

// ---------------- packed f32x2 helpers (Blackwell FFMA2) -------------------
#define FMA2(d, a, b, c) \
    asm("fma.rn.f32x2 %0, %1, %2, %3;" : "=l"(d) : "l"(a), "l"(b), "l"(c))
#define PACK2(d, f) \
    asm("mov.b64 %0, {%1, %1};" : "=l"(d) : "r"(__float_as_uint(f)))
#define UNPACK2(lo, hi, p) \
    asm("mov.b64 {%0, %1}, %2;" : "=f"(lo), "=f"(hi) : "l"(p))

// ---------------- dtype detection + fused convert/count -------------------
__global__ void k_detect(const int* __restrict__ raw) {
    __shared__ int nz;
    int t = threadIdx.x;              // 128 threads
    if (t == 0) nz = 0;
    __syncthreads();
    if (raw[2 * t + 1] != 0) atomicAdd(&nz, 1);
    __syncthreads();
    if (t == 0) g_is64 = (nz == 0) ? 1 : 0;
}

__global__ void k_zero_cnt() {
    int i = blockIdx.x * blockDim.x + threadIdx.x;
    if (i < N_NODES) g_cnt[i] = 0;
}

__global__ void k_convert_count(const void* __restrict__ ei) {
    int i = blockIdx.x * blockDim.x + threadIdx.x;
    if (i >= N_EDGES) return;
    int s, d;
    if (g_is64) {
        const long long* e = (const long long*)ei;
        s = (int)e[i];
        d = (int)e[N_EDGES + i];
    } else {
        const int* e = (const int*)ei;
        s = e[i];
        d = e[N_EDGES + i];
    }
    if ((unsigned)s >= N_NODES) s = 0;   // defensive
    if ((unsigned)d >= N_NODES) d = 0;
    g_src[i] = s;
    g_dst[i] = d;
    atomicAdd(&g_cnt[d], 1);
}

// ---------------- 3-kernel chunked scan ------------------------------------
__global__ void k_scan_a() {            // per-block sums of g_cnt
    int i = blockIdx.x * 256 + threadIdx.x;
    int v = (i < N_NODES) ? g_cnt[i] : 0;
    __shared__ int wsum[8];
    int lane = threadIdx.x & 31, w = threadIdx.x >> 5;
    #pragma unroll
    for (int off = 16; off; off >>= 1) v += __shfl_down_sync(0xffffffffu, v, off);
    if (lane == 0) wsum[w] = v;
    __syncthreads();
    if (w == 0) {
        int s = (lane < 8) ? wsum[lane] : 0;
        #pragma unroll
        for (int off = 4; off; off >>= 1) s += __shfl_down_sync(0xffffffffu, s, off);
        if (lane == 0) g_bsum[blockIdx.x] = s;
    }
}

__global__ void k_scan_b() {            // exclusive scan of 196 block sums
    int t = threadIdx.x;                // 256 threads
    int v = (t < NODE_BLKS) ? g_bsum[t] : 0;
    int s = v;
    int lane = t & 31, w = t >> 5;
    __shared__ int wsum[8];
    #pragma unroll
    for (int off = 1; off < 32; off <<= 1) {
        int n = __shfl_up_sync(0xffffffffu, s, off);
        if (lane >= off) s += n;
    }
    if (lane == 31) wsum[w] = s;
    __syncthreads();
    if (t == 0) {
        int acc = 0;
        #pragma unroll
        for (int i = 0; i < 8; i++) { int tmp = wsum[i]; wsum[i] = acc; acc += tmp; }
    }
    __syncthreads();
    if (t < NODE_BLKS) g_boff[t] = s - v + wsum[w];
}

__global__ void k_scan_c() {            // rowptr + dinv
    int i = blockIdx.x * 256 + threadIdx.x;
    int v = (i < N_NODES) ? g_cnt[i] : 0;
    int s = v;
    int lane = threadIdx.x & 31, w = threadIdx.x >> 5;
    __shared__ int wsum[8];
    #pragma unroll
    for (int off = 1; off < 32; off <<= 1) {
        int n = __shfl_up_sync(0xffffffffu, s, off);
        if (lane >= off) s += n;
    }
    if (lane == 31) wsum[w] = s;
    __syncthreads();
    if (threadIdx.x == 0) {
        int acc = 0;
        #pragma unroll
        for (int j = 0; j < 8; j++) { int tmp = wsum[j]; wsum[j] = acc; acc += tmp; }
    }
    __syncthreads();
    if (i < N_NODES) {
        g_rowptr[i + 1] = g_boff[blockIdx.x] + wsum[w] + s;   // inclusive
        g_dinv[i] = rsqrtf((float)(v + 1));                   // +1 self loop
    }
    if (i == 0) g_rowptr[0] = 0;
}

__global__ void k_fill_csr() {          // consumes g_cnt as fill cursor
    int i = blockIdx.x * blockDim.x + threadIdx.x;
    if (i < N_EDGES) {
        int d = g_dst[i];
        int r = atomicSub(&g_cnt[d], 1);            // r = remaining slots
        int pos = g_rowptr[d] + r - 1;
        if ((unsigned)pos < N_EDGES) g_col[pos] = g_src[i];
    }
}

// ---------------- GEMM: scratch[r][c] = dinv[r] * sum_k A[r][k] W[k][c] ----
// 128x64 tile per block, 256 threads, K-chunk 32.
// A staged TRANSPOSED in smem (At[k][row]) so ulonglong2 loads give packed
// row-pairs directly; inner loop = 16x fma.rn.f32x2 (FFMA2) per k.
template <int K, bool SRC_Z1, int DST>
__global__ void k_gemm_scale(const float* __restrict__ Ain,
                             const float* __restrict__ W) {
    const float* A  = SRC_Z1 ? (const float*)g_z1 : Ain;
    float*      out = (DST == 0) ? g_hs1 : g_hs2;

    __shared__ float At[32][132];   // [k][row], 128 rows + pad (16B-aligned stride)
    __shared__ float Ws[32][68];    // [k][col], 64 cols + pad

    const int row0 = blockIdx.x * 128;
    const int tid  = threadIdx.x;
    const int tx   = tid & 15;      // 4 cols:  tx*4 .. tx*4+3
    const int ty   = tid >> 4;      // 8 rows:  ty*8 .. ty*8+7 (4 row-pairs)

    unsigned long long acc[4][4];   // [row-pair][col], packed f32x2
    #pragma unroll
    for (int p = 0; p < 4; p++)
        #pragma unroll
        for (int c = 0; c < 4; c++) acc[p][c] = 0ULL;

    for (int kc = 0; kc < K; kc += 32) {
        if (kc) __syncthreads();
        // Ws: 32x64 floats = 512 float4, 2 per thread
        #pragma unroll
        for (int l = 0; l < 2; l++) {
            int j  = tid + l * 256;
            int k  = j >> 4;
            int c4 = (j & 15) << 2;
            float4 v = *(const float4*)(W + (size_t)(kc + k) * 64 + c4);
            *(float4*)&Ws[k][c4] = v;
        }
        // At: 128 rows x 32 k = 1024 float4, 4 per thread, transposed scatter
        #pragma unroll
        for (int l = 0; l < 4; l++) {
            int j  = tid + l * 256;
            int r  = j >> 3;             // 0..127
            int k4 = (j & 7) << 2;       // 0..28
            float4 v = make_float4(0.f, 0.f, 0.f, 0.f);
            int row = row0 + r;
            if (row < N_NODES)
                v = *(const float4*)(A + (size_t)row * K + kc + k4);
            At[k4 + 0][r] = v.x;
            At[k4 + 1][r] = v.y;
            At[k4 + 2][r] = v.z;
            At[k4 + 3][r] = v.w;
        }
        __syncthreads();

        #pragma unroll 8
        for (int k = 0; k < 32; k++) {
            ulonglong2 a01 = *(const ulonglong2*)&At[k][ty * 8];     // rows 0-3
            ulonglong2 a23 = *(const ulonglong2*)&At[k][ty * 8 + 4]; // rows 4-7
            float4 b = *(const float4*)&Ws[k][tx * 4];
            unsigned long long B0, B1, B2, B3;
            PACK2(B0, b.x); PACK2(B1, b.y); PACK2(B2, b.z); PACK2(B3, b.w);
            FMA2(acc[0][0], a01.x, B0, acc[0][0]);
            FMA2(acc[0][1], a01.x, B1, acc[0][1]);
            FMA2(acc[0][2], a01.x, B2, acc[0][2]);
            FMA2(acc[0][3], a01.x, B3, acc[0][3]);
            FMA2(acc[1][0], a01.y, B0, acc[1][0]);
            FMA2(acc[1][1], a01.y, B1, acc[1][1]);
            FMA2(acc[1][2], a01.y, B2, acc[1][2]);
            FMA2(acc[1][3], a01.y, B3, acc[1][3]);
            FMA2(acc[2][0], a23.x, B0, acc[2][0]);
            FMA2(acc[2][1], a23.x, B1, acc[2][1]);
            FMA2(acc[2][2], a23.x, B2, acc[2][2]);
            FMA2(acc[2][3], a23.x, B3, acc[2][3]);
            FMA2(acc[3][0], a23.y, B0, acc[3][0]);
            FMA2(acc[3][1], a23.y, B1, acc[3][1]);
            FMA2(acc[3][2], a23.y, B2, acc[3][2]);
            FMA2(acc[3][3], a23.y, B3, acc[3][3]);
        }
    }

    #pragma unroll
    for (int p = 0; p < 4; p++) {
        float lo0, hi0, lo1, hi1, lo2, hi2, lo3, hi3;
        UNPACK2(lo0, hi0, acc[p][0]);
        UNPACK2(lo1, hi1, acc[p][1]);
        UNPACK2(lo2, hi2, acc[p][2]);
        UNPACK2(lo3, hi3, acc[p][3]);
        int r0 = row0 + ty * 8 + p * 2;
        if (r0 < N_NODES) {
            float dv = g_dinv[r0];
            *(float4*)(out + (size_t)r0 * 64 + tx * 4) =
                make_float4(lo0 * dv, lo1 * dv, lo2 * dv, lo3 * dv);
        }
        if (r0 + 1 < N_NODES) {
            float dv = g_dinv[r0 + 1];
            *(float4*)(out + (size_t)(r0 + 1) * 64 + tx * 4) =
                make_float4(hi0 * dv, hi1 * dv, hi2 * dv, hi3 * dv);
        }
    }
}

// ---------------- aggregation: one warp per destination node --------------
// out[d] = dinv[d] * (hs[d] + sum_{e: dst=d} hs[col[e]]) + b  (+ReLU)
template <bool LAYER2>
__global__ void k_aggregate(const float* __restrict__ bias,
                            float* __restrict__ outp) {
    int gw   = (blockIdx.x * blockDim.x + threadIdx.x) >> 5;
    int lane = threadIdx.x & 31;
    if (gw >= N_NODES) return;

    const float2* h2 = (const float2*)(LAYER2 ? g_hs2 : g_hs1);
    float2*       o2 = LAYER2 ? (float2*)outp : (float2*)g_z1;

    float2 acc = h2[(size_t)gw * 32 + lane];   // self loop term

    int e   = g_rowptr[gw];
    int end = g_rowptr[gw + 1];

    for (; e + 3 < end; e += 4) {
        int s0 = g_col[e + 0];
        int s1 = g_col[e + 1];
        int s2 = g_col[e + 2];
        int s3 = g_col[e + 3];
        float2 v0 = h2[(size_t)s0 * 32 + lane];
        float2 v1 = h2[(size_t)s1 * 32 + lane];
        float2 v2 = h2[(size_t)s2 * 32 + lane];
        float2 v3 = h2[(size_t)s3 * 32 + lane];
        acc.x += v0.x + v1.x + v2.x + v3.x;
        acc.y += v0.y + v1.y + v2.y + v3.y;
    }
    for (; e < end; e++) {
        int s = g_col[e];
        float2 v = h2[(size_t)s * 32 + lane];
        acc.x += v.x; acc.y += v.y;
    }

    float  dv = g_dinv[gw];
    float2 bb = ((const float2*)bias)[lane];
    float ox = fmaf(acc.x, dv, bb.x);
    float oy = fmaf(acc.y, dv, bb.y);
    if (!LAYER2) { ox = fmaxf(ox, 0.0f); oy = fmaxf(oy, 0.0f); }
    o2[(size_t)gw * 32 + lane] = make_float2(ox, oy);
}

// ---------------- launch ---------------------------------------------------
extern "C" void kernel_launch(void* const* d_in, const int* in_sizes, int n_in,
                              void* d_out, int out_size) {
    const float* x  = (const float*)d_in[0];
    const void*  ei = d_in[1];                 // int32 OR int64 [2, 800000]
    const float* W1 = (const float*)d_in[2];
    const float* b1 = (const float*)d_in[3];
    const float* W2 = (const float*)d_in[4];
    const float* b2 = (const float*)d_in[5];
    float*      out = (float*)d_out;

    const int TB = 256;
    const int edgeBlocks = (N_EDGES + TB - 1) / TB;      // 3125
    const int gemmBlocks = (N_NODES + 127) / 128;        // 391
    const int aggBlocks  = (N_NODES * 32 + TB - 1) / TB; // 6250

    k_detect<<<1, 128>>>((const int*)ei);
    k_zero_cnt<<<NODE_BLKS, TB>>>();
    k_convert_count<<<edgeBlocks, TB>>>(ei);
    k_scan_a<<<NODE_BLKS, TB>>>();
    k_scan_b<<<1, TB>>>();
    k_scan_c<<<NODE_BLKS, TB>>>();
    k_fill_csr<<<edgeBlocks, TB>>>();

    // layer 1: h = (x @ W1) * dinv -> aggregate (+bias, ReLU) -> g_z1
    k_gemm_scale<IN_C, false, 0><<<gemmBlocks, TB>>>(x, W1);
    k_aggregate<false><<<aggBlocks, TB>>>(b1, nullptr);

    // layer 2: h = (g_z1 @ W2) * dinv -> aggregate (+bias) -> out
    k_gemm_scale<HID_C, true, 1><<<gemmBlocks, TB>>>(nullptr, W2);
    k_aggregate<true><<<aggBlocks, TB>>>(b2, out);
}

// round 6
// speedup vs baseline: 1.9298x; 1.1605x over previous
#include <cuda_runtime.h>
#include <cuda_fp16.h>

#define N_NODES 50000
#define N_EDGES 800000
#define IN_C    128
#define HID_C   64
#define OUT_C   64
#define GEMM_BLKS 391    // ceil(50000/128)
#define EDGE_BLKS 3125   // ceil(800000/256)
#define SCAN_BLKS 196    // ceil(50000/256)

// ---------------- scratch (static device globals; no allocations) ----------
// g_cnt: starts 0 (static init), k_fill_csr drains it back to 0 every run.
// g_bsum: reset to 0 inside K1 every run (scan publishes value+1 as self-flag).
__device__ int g_src[N_EDGES];
__device__ int g_dst[N_EDGES];
__device__ int g_cnt[N_NODES];
__device__ int g_bsum[SCAN_BLKS];
__device__ int g_rowptr[N_NODES + 1];
__device__ int g_col[N_EDGES];
__device__ __align__(16) float  g_dinv[N_NODES];
__device__ __align__(16) __half g_h1[N_NODES * HID_C];   // layer-1 h (UNscaled), fp16
__device__ __align__(16) float  g_z1[N_NODES * HID_C];   // layer-1 output, fp32
__device__ __align__(16) __half g_h2[N_NODES * OUT_C];   // layer-2 h*dinv, fp16

// ---------------- packed f32x2 helpers (Blackwell FFMA2) -------------------
#define FMA2(d, a, b, c) \
    asm("fma.rn.f32x2 %0, %1, %2, %3;" : "=l"(d) : "l"(a), "l"(b), "l"(c))
#define PACK2(d, f) \
    asm("mov.b64 %0, {%1, %1};" : "=l"(d) : "r"(__float_as_uint(f)))
#define UNPACK2(lo, hi, p) \
    asm("mov.b64 {%0, %1}, %2;" : "=f"(lo), "=f"(hi) : "l"(p))

static __device__ __forceinline__ unsigned packh(float a, float b) {
    __half2 h = __floats2half2_rn(a, b);
    return *reinterpret_cast<unsigned*>(&h);
}

// ---------------- GEMM body: 128x64 tile, K-chunk 32, FFMA2 ---------------
// outh[r][c] = (SCALE ? dinv[r] : 1) * sum_k A[r][k] W[k][c], stored fp16
template <int K, bool SCALE>
__device__ __forceinline__ void gemm_body(const float* __restrict__ A,
                                          const float* __restrict__ W,
                                          __half* __restrict__ outh,
                                          float At[32][132], float Ws[32][68],
                                          int row0) {
    const int tid = threadIdx.x;
    const int tx  = tid & 15;       // 4 cols:  tx*4 .. tx*4+3
    const int ty  = tid >> 4;       // 8 rows:  ty*8 .. ty*8+7 (4 row-pairs)

    unsigned long long acc[4][4];
    #pragma unroll
    for (int p = 0; p < 4; p++)
        #pragma unroll
        for (int c = 0; c < 4; c++) acc[p][c] = 0ULL;

    for (int kc = 0; kc < K; kc += 32) {
        if (kc) __syncthreads();
        #pragma unroll
        for (int l = 0; l < 2; l++) {                   // Ws: 32x64
            int j  = tid + l * 256;
            int k  = j >> 4;
            int c4 = (j & 15) << 2;
            *(float4*)&Ws[k][c4] = *(const float4*)(W + (size_t)(kc + k) * 64 + c4);
        }
        #pragma unroll
        for (int l = 0; l < 4; l++) {                   // At: transposed 128x32
            int j  = tid + l * 256;
            int r  = j >> 3;
            int k4 = (j & 7) << 2;
            float4 v = make_float4(0.f, 0.f, 0.f, 0.f);
            int row = row0 + r;
            if (row < N_NODES)
                v = *(const float4*)(A + (size_t)row * K + kc + k4);
            At[k4 + 0][r] = v.x;
            At[k4 + 1][r] = v.y;
            At[k4 + 2][r] = v.z;
            At[k4 + 3][r] = v.w;
        }
        __syncthreads();

        #pragma unroll 8
        for (int k = 0; k < 32; k++) {
            ulonglong2 a01 = *(const ulonglong2*)&At[k][ty * 8];
            ulonglong2 a23 = *(const ulonglong2*)&At[k][ty * 8 + 4];
            float4 b = *(const float4*)&Ws[k][tx * 4];
            unsigned long long B0, B1, B2, B3;
            PACK2(B0, b.x); PACK2(B1, b.y); PACK2(B2, b.z); PACK2(B3, b.w);
            FMA2(acc[0][0], a01.x, B0, acc[0][0]);
            FMA2(acc[0][1], a01.x, B1, acc[0][1]);
            FMA2(acc[0][2], a01.x, B2, acc[0][2]);
            FMA2(acc[0][3], a01.x, B3, acc[0][3]);
            FMA2(acc[1][0], a01.y, B0, acc[1][0]);
            FMA2(acc[1][1], a01.y, B1, acc[1][1]);
            FMA2(acc[1][2], a01.y, B2, acc[1][2]);
            FMA2(acc[1][3], a01.y, B3, acc[1][3]);
            FMA2(acc[2][0], a23.x, B0, acc[2][0]);
            FMA2(acc[2][1], a23.x, B1, acc[2][1]);
            FMA2(acc[2][2], a23.x, B2, acc[2][2]);
            FMA2(acc[2][3], a23.x, B3, acc[2][3]);
            FMA2(acc[3][0], a23.y, B0, acc[3][0]);
            FMA2(acc[3][1], a23.y, B1, acc[3][1]);
            FMA2(acc[3][2], a23.y, B2, acc[3][2]);
            FMA2(acc[3][3], a23.y, B3, acc[3][3]);
        }
    }

    #pragma unroll
    for (int p = 0; p < 4; p++) {
        float lo0, hi0, lo1, hi1, lo2, hi2, lo3, hi3;
        UNPACK2(lo0, hi0, acc[p][0]);
        UNPACK2(lo1, hi1, acc[p][1]);
        UNPACK2(lo2, hi2, acc[p][2]);
        UNPACK2(lo3, hi3, acc[p][3]);
        int r0 = row0 + ty * 8 + p * 2;
        if (r0 < N_NODES) {
            float s = SCALE ? g_dinv[r0] : 1.0f;
            *(uint2*)(outh + (size_t)r0 * 64 + tx * 4) =
                make_uint2(packh(lo0 * s, lo1 * s), packh(lo2 * s, lo3 * s));
        }
        if (r0 + 1 < N_NODES) {
            float s = SCALE ? g_dinv[r0 + 1] : 1.0f;
            *(uint2*)(outh + (size_t)(r0 + 1) * 64 + tx * 4) =
                make_uint2(packh(hi0 * s, hi1 * s), packh(hi2 * s, hi3 * s));
        }
    }
}

// ---------------- K1: fused [GEMM1 | convert+count] ------------------------
__global__ void k1_fused(const float* __restrict__ x,
                         const float* __restrict__ W1,
                         const void* __restrict__ ei) {
    __shared__ float At[32][132];
    __shared__ float Ws[32][68];
    if (blockIdx.x < GEMM_BLKS) {
        gemm_body<IN_C, false>(x, W1, g_h1, At, Ws, blockIdx.x * 128);
    } else {
        __shared__ int s_nz;
        const int tid = threadIdx.x;
        const int cb  = blockIdx.x - GEMM_BLKS;
        if (tid == 0) s_nz = 0;
        __syncthreads();
        // dtype detection: int64 ids < 2^31 -> all odd 32-bit words zero
        if (tid < 128 && ((const int*)ei)[2 * tid + 1] != 0) atomicAdd(&s_nz, 1);
        __syncthreads();
        const bool is64 = (s_nz == 0);
        if (cb == 0 && tid < SCAN_BLKS) g_bsum[tid] = 0;   // reset scan flags
        int i = cb * 256 + tid;
        if (i < N_EDGES) {
            int s, d;
            if (is64) {
                const long long* e = (const long long*)ei;
                s = (int)e[i];
                d = (int)e[N_EDGES + i];
            } else {
                const int* e = (const int*)ei;
                s = e[i];
                d = e[N_EDGES + i];
            }
            if ((unsigned)s >= N_NODES) s = 0;   // defensive
            if ((unsigned)d >= N_NODES) d = 0;
            g_src[i] = s;
            g_dst[i] = d;
            atomicAdd(&g_cnt[d], 1);
        }
    }
}

// ---------------- single-kernel decoupled-lookback scan --------------------
__global__ void k_scan() {
    const int b = blockIdx.x, tid = threadIdx.x;
    const int i = b * 256 + tid;
    int v = (i < N_NODES) ? g_cnt[i] : 0;
    const int lane = tid & 31, w = tid >> 5;
    __shared__ int wsum[8];
    __shared__ int s_total, s_prefix;

    int s = v;
    #pragma unroll
    for (int off = 1; off < 32; off <<= 1) {
        int n = __shfl_up_sync(0xffffffffu, s, off);
        if (lane >= off) s += n;
    }
    if (lane == 31) wsum[w] = s;
    __syncthreads();
    if (tid == 0) {
        int acc = 0;
        #pragma unroll
        for (int j = 0; j < 8; j++) { int t = wsum[j]; wsum[j] = acc; acc += t; }
        s_total = acc;
    }
    __syncthreads();
    int incl = wsum[w] + s;               // block-local inclusive prefix

    if (tid == 0) atomicExch(&g_bsum[b], s_total + 1);   // publish (self-flag)
    if (tid < 32) {                        // lookback over predecessors
        int part = 0;
        for (int j = tid; j < b; j += 32) {
            int val;
            do { val = *(volatile int*)&g_bsum[j]; } while (val == 0);
            part += val - 1;
        }
        #pragma unroll
        for (int off = 16; off; off >>= 1)
            part += __shfl_down_sync(0xffffffffu, part, off);
        if (tid == 0) s_prefix = part;
    }
    __syncthreads();

    if (i < N_NODES) {
        g_rowptr[i + 1] = s_prefix + incl;
        g_dinv[i] = rsqrtf((float)(v + 1));   // +1 self loop
    }
    if (i == 0) g_rowptr[0] = 0;
}

// ---------------- CSR fill (drains g_cnt back to zero) ---------------------
__global__ void k_fill_csr() {
    int i = blockIdx.x * blockDim.x + threadIdx.x;
    if (i < N_EDGES) {
        int d = g_dst[i];
        int r = atomicSub(&g_cnt[d], 1);
        int pos = g_rowptr[d] + r - 1;
        if ((unsigned)pos < N_EDGES) g_col[pos] = g_src[i];
    }
}

// ---------------- aggregation: one warp per destination node ---------------
// layer1 (LAYER2=false): acc = h1[d]*dinv[d] + sum h1[s]*dinv[s];
//                        z1[d] = relu(dinv[d]*acc + b1)   (fp32 out)
// layer2 (LAYER2=true):  acc = h2[d] + sum h2[s];  out = dinv[d]*acc + b2
template <bool LAYER2>
__global__ void k_aggregate(const float* __restrict__ bias,
                            float* __restrict__ outp) {
    int gw   = (blockIdx.x * blockDim.x + threadIdx.x) >> 5;
    int lane = threadIdx.x & 31;
    if (gw >= N_NODES) return;

    const __half2* h2 = (const __half2*)(LAYER2 ? g_h2 : g_h1);
    float2*        o2 = LAYER2 ? (float2*)outp : (float2*)g_z1;

    float dvd = g_dinv[gw];
    float2 acc;
    {
        float2 hv = __half22float2(h2[(size_t)gw * 32 + lane]);
        float wgt = LAYER2 ? 1.0f : dvd;   // layer-1 self term: h*dinv[d]
        acc.x = hv.x * wgt;
        acc.y = hv.y * wgt;
    }

    int e   = g_rowptr[gw];
    int end = g_rowptr[gw + 1];

    for (; e + 3 < end; e += 4) {
        int s0 = g_col[e + 0];
        int s1 = g_col[e + 1];
        int s2 = g_col[e + 2];
        int s3 = g_col[e + 3];
        float2 v0 = __half22float2(h2[(size_t)s0 * 32 + lane]);
        float2 v1 = __half22float2(h2[(size_t)s1 * 32 + lane]);
        float2 v2 = __half22float2(h2[(size_t)s2 * 32 + lane]);
        float2 v3 = __half22float2(h2[(size_t)s3 * 32 + lane]);
        if (!LAYER2) {
            float d0 = g_dinv[s0], d1 = g_dinv[s1], d2 = g_dinv[s2], d3 = g_dinv[s3];
            acc.x += v0.x * d0 + v1.x * d1 + v2.x * d2 + v3.x * d3;
            acc.y += v0.y * d0 + v1.y * d1 + v2.y * d2 + v3.y * d3;
        } else {
            acc.x += v0.x + v1.x + v2.x + v3.x;
            acc.y += v0.y + v1.y + v2.y + v3.y;
        }
    }
    for (; e < end; e++) {
        int s = g_col[e];
        float2 v = __half22float2(h2[(size_t)s * 32 + lane]);
        float dw = LAYER2 ? 1.0f : g_dinv[s];
        acc.x += v.x * dw;
        acc.y += v.y * dw;
    }

    float2 bb = ((const float2*)bias)[lane];
    float ox = fmaf(acc.x, dvd, bb.x);
    float oy = fmaf(acc.y, dvd, bb.y);
    if (!LAYER2) { ox = fmaxf(ox, 0.0f); oy = fmaxf(oy, 0.0f); }
    o2[(size_t)gw * 32 + lane] = make_float2(ox, oy);
}

// ---------------- GEMM2 standalone -----------------------------------------
__global__ void k_gemm2(const float* __restrict__ W2) {
    __shared__ float At[32][132];
    __shared__ float Ws[32][68];
    gemm_body<HID_C, true>(g_z1, W2, g_h2, At, Ws, blockIdx.x * 128);
}

// ---------------- launch ---------------------------------------------------
extern "C" void kernel_launch(void* const* d_in, const int* in_sizes, int n_in,
                              void* d_out, int out_size) {
    const float* x  = (const float*)d_in[0];
    const void*  ei = d_in[1];                 // int32 OR int64 [2, 800000]
    const float* W1 = (const float*)d_in[2];
    const float* b1 = (const float*)d_in[3];
    const float* W2 = (const float*)d_in[4];
    const float* b2 = (const float*)d_in[5];
    float*      out = (float*)d_out;

    const int TB = 256;
    const int aggBlocks = (N_NODES * 32 + TB - 1) / TB;   // 6250

    k1_fused<<<GEMM_BLKS + EDGE_BLKS, TB>>>(x, W1, ei);   // GEMM1 || convert+count
    k_scan<<<SCAN_BLKS, TB>>>();                          // rowptr + dinv
    k_fill_csr<<<EDGE_BLKS, TB>>>();                      // CSR columns
    k_aggregate<false><<<aggBlocks, TB>>>(b1, nullptr);   // -> g_z1 (ReLU)
    k_gemm2<<<GEMM_BLKS, TB>>>(W2);                       // -> g_h2 (dinv-scaled)
    k_aggregate<true><<<aggBlocks, TB>>>(b2, out);        // -> out
}

// round 7
// speedup vs baseline: 2.0200x; 1.0467x over previous
#include <cuda_runtime.h>
#include <cuda_fp16.h>

#define N_NODES 50000
#define N_EDGES 800000
#define IN_C    128
#define HID_C   64
#define OUT_C   64
#define GEMM_BLKS 391    // ceil(50000/128)
#define EDGE_BLKS 3125   // ceil(800000/256)
#define SCAN_BLKS 196    // ceil(50000/256)

// ---------------- scratch (static device globals; no allocations) ----------
// g_cnt: starts 0 (static init), k_fill_csr drains it back to 0 every run.
// g_bsum: reset to 0 inside k_convert_count every run.
__device__ int g_src[N_EDGES];
__device__ int g_dst[N_EDGES];
__device__ int g_cnt[N_NODES];
__device__ int g_bsum[SCAN_BLKS];
__device__ int g_rowptr[N_NODES + 1];
__device__ int g_col[N_EDGES];
__device__ __align__(16) float  g_dinv[N_NODES];
__device__ __align__(16) __half g_h1[N_NODES * HID_C];   // layer-1 h*dinv, fp16
__device__ __align__(16) float  g_z1[N_NODES * HID_C];   // layer-1 output, fp32
__device__ __align__(16) __half g_h2[N_NODES * OUT_C];   // layer-2 h*dinv, fp16

// ---------------- packed f32x2 helpers (Blackwell FFMA2) -------------------
#define FMA2(d, a, b, c) \
    asm("fma.rn.f32x2 %0, %1, %2, %3;" : "=l"(d) : "l"(a), "l"(b), "l"(c))
#define PACK2(d, f) \
    asm("mov.b64 %0, {%1, %1};" : "=l"(d) : "r"(__float_as_uint(f)))
#define UNPACK2(lo, hi, p) \
    asm("mov.b64 {%0, %1}, %2;" : "=f"(lo), "=f"(hi) : "l"(p))

static __device__ __forceinline__ unsigned packh(float a, float b) {
    __half2 h = __floats2half2_rn(a, b);
    return *reinterpret_cast<unsigned*>(&h);
}

// ---------------- GEMM body: 128x64 tile, K-chunk 32, FFMA2 ---------------
// outh[r][c] = dinv[r] * sum_k A[r][k] W[k][c], stored fp16
template <int K>
__device__ __forceinline__ void gemm_body(const float* __restrict__ A,
                                          const float* __restrict__ W,
                                          __half* __restrict__ outh,
                                          float At[32][132], float Ws[32][68],
                                          int row0) {
    const int tid = threadIdx.x;
    const int tx  = tid & 15;       // 4 cols:  tx*4 .. tx*4+3
    const int ty  = tid >> 4;       // 8 rows:  ty*8 .. ty*8+7 (4 row-pairs)

    unsigned long long acc[4][4];
    #pragma unroll
    for (int p = 0; p < 4; p++)
        #pragma unroll
        for (int c = 0; c < 4; c++) acc[p][c] = 0ULL;

    for (int kc = 0; kc < K; kc += 32) {
        if (kc) __syncthreads();
        #pragma unroll
        for (int l = 0; l < 2; l++) {                   // Ws: 32x64
            int j  = tid + l * 256;
            int k  = j >> 4;
            int c4 = (j & 15) << 2;
            *(float4*)&Ws[k][c4] = *(const float4*)(W + (size_t)(kc + k) * 64 + c4);
        }
        #pragma unroll
        for (int l = 0; l < 4; l++) {                   // At: transposed 128x32
            int j  = tid + l * 256;
            int r  = j >> 3;
            int k4 = (j & 7) << 2;
            float4 v = make_float4(0.f, 0.f, 0.f, 0.f);
            int row = row0 + r;
            if (row < N_NODES)
                v = *(const float4*)(A + (size_t)row * K + kc + k4);
            At[k4 + 0][r] = v.x;
            At[k4 + 1][r] = v.y;
            At[k4 + 2][r] = v.z;
            At[k4 + 3][r] = v.w;
        }
        __syncthreads();

        #pragma unroll 8
        for (int k = 0; k < 32; k++) {
            ulonglong2 a01 = *(const ulonglong2*)&At[k][ty * 8];
            ulonglong2 a23 = *(const ulonglong2*)&At[k][ty * 8 + 4];
            float4 b = *(const float4*)&Ws[k][tx * 4];
            unsigned long long B0, B1, B2, B3;
            PACK2(B0, b.x); PACK2(B1, b.y); PACK2(B2, b.z); PACK2(B3, b.w);
            FMA2(acc[0][0], a01.x, B0, acc[0][0]);
            FMA2(acc[0][1], a01.x, B1, acc[0][1]);
            FMA2(acc[0][2], a01.x, B2, acc[0][2]);
            FMA2(acc[0][3], a01.x, B3, acc[0][3]);
            FMA2(acc[1][0], a01.y, B0, acc[1][0]);
            FMA2(acc[1][1], a01.y, B1, acc[1][1]);
            FMA2(acc[1][2], a01.y, B2, acc[1][2]);
            FMA2(acc[1][3], a01.y, B3, acc[1][3]);
            FMA2(acc[2][0], a23.x, B0, acc[2][0]);
            FMA2(acc[2][1], a23.x, B1, acc[2][1]);
            FMA2(acc[2][2], a23.x, B2, acc[2][2]);
            FMA2(acc[2][3], a23.x, B3, acc[2][3]);
            FMA2(acc[3][0], a23.y, B0, acc[3][0]);
            FMA2(acc[3][1], a23.y, B1, acc[3][1]);
            FMA2(acc[3][2], a23.y, B2, acc[3][2]);
            FMA2(acc[3][3], a23.y, B3, acc[3][3]);
        }
    }

    #pragma unroll
    for (int p = 0; p < 4; p++) {
        float lo0, hi0, lo1, hi1, lo2, hi2, lo3, hi3;
        UNPACK2(lo0, hi0, acc[p][0]);
        UNPACK2(lo1, hi1, acc[p][1]);
        UNPACK2(lo2, hi2, acc[p][2]);
        UNPACK2(lo3, hi3, acc[p][3]);
        int r0 = row0 + ty * 8 + p * 2;
        if (r0 < N_NODES) {
            float s = g_dinv[r0];
            *(uint2*)(outh + (size_t)r0 * 64 + tx * 4) =
                make_uint2(packh(lo0 * s, lo1 * s), packh(lo2 * s, lo3 * s));
        }
        if (r0 + 1 < N_NODES) {
            float s = g_dinv[r0 + 1];
            *(uint2*)(outh + (size_t)(r0 + 1) * 64 + tx * 4) =
                make_uint2(packh(hi0 * s, hi1 * s), packh(hi2 * s, hi3 * s));
        }
    }
}

// ---------------- K1: convert + degree count (+ scan-flag reset) -----------
__global__ void k_convert_count(const void* __restrict__ ei) {
    __shared__ int s_nz;
    const int tid = threadIdx.x;
    if (tid == 0) s_nz = 0;
    __syncthreads();
    // dtype detection: int64 ids < 2^31 -> all odd 32-bit words zero
    if (tid < 128 && ((const int*)ei)[2 * tid + 1] != 0) atomicAdd(&s_nz, 1);
    __syncthreads();
    const bool is64 = (s_nz == 0);
    if (blockIdx.x == 0 && tid < SCAN_BLKS) g_bsum[tid] = 0;
    int i = blockIdx.x * 256 + tid;
    if (i < N_EDGES) {
        int s, d;
        if (is64) {
            const long long* e = (const long long*)ei;
            s = (int)e[i];
            d = (int)e[N_EDGES + i];
        } else {
            const int* e = (const int*)ei;
            s = e[i];
            d = e[N_EDGES + i];
        }
        if ((unsigned)s >= N_NODES) s = 0;   // defensive
        if ((unsigned)d >= N_NODES) d = 0;
        g_src[i] = s;
        g_dst[i] = d;
        atomicAdd(&g_cnt[d], 1);
    }
}

// ---------------- K2: single-kernel decoupled-lookback scan ----------------
__global__ void k_scan() {
    const int b = blockIdx.x, tid = threadIdx.x;
    const int i = b * 256 + tid;
    int v = (i < N_NODES) ? g_cnt[i] : 0;
    const int lane = tid & 31, w = tid >> 5;
    __shared__ int wsum[8];
    __shared__ int s_total, s_prefix;

    int s = v;
    #pragma unroll
    for (int off = 1; off < 32; off <<= 1) {
        int n = __shfl_up_sync(0xffffffffu, s, off);
        if (lane >= off) s += n;
    }
    if (lane == 31) wsum[w] = s;
    __syncthreads();
    if (tid == 0) {
        int acc = 0;
        #pragma unroll
        for (int j = 0; j < 8; j++) { int t = wsum[j]; wsum[j] = acc; acc += t; }
        s_total = acc;
    }
    __syncthreads();
    int incl = wsum[w] + s;               // block-local inclusive prefix

    if (tid == 0) atomicExch(&g_bsum[b], s_total + 1);   // publish (self-flag)
    if (tid < 32) {                        // lookback over predecessors
        int part = 0;
        for (int j = tid; j < b; j += 32) {
            int val;
            do { val = *(volatile int*)&g_bsum[j]; } while (val == 0);
            part += val - 1;
        }
        #pragma unroll
        for (int off = 16; off; off >>= 1)
            part += __shfl_down_sync(0xffffffffu, part, off);
        if (tid == 0) s_prefix = part;
    }
    __syncthreads();

    if (i < N_NODES) {
        g_rowptr[i + 1] = s_prefix + incl;
        g_dinv[i] = rsqrtf((float)(v + 1));   // +1 self loop
    }
    if (i == 0) g_rowptr[0] = 0;
}

// ---------------- K3: fused [GEMM1(*dinv) | CSR fill] ----------------------
__global__ void k3_fused(const float* __restrict__ x,
                         const float* __restrict__ W1) {
    if (blockIdx.x < GEMM_BLKS) {
        __shared__ float At[32][132];
        __shared__ float Ws[32][68];
        gemm_body<IN_C>(x, W1, g_h1, At, Ws, blockIdx.x * 128);
    } else {
        int i = (blockIdx.x - GEMM_BLKS) * 256 + threadIdx.x;
        if (i < N_EDGES) {
            int d = g_dst[i];
            int r = atomicSub(&g_cnt[d], 1);   // drains g_cnt back to 0
            int pos = g_rowptr[d] + r - 1;
            if ((unsigned)pos < N_EDGES) g_col[pos] = g_src[i];
        }
    }
}

// ---------------- aggregation: one warp per destination node ---------------
// hs holds h*dinv (pre-scaled); out[d] = dinv[d] * (hs[d] + sum hs[col]) + b
// Indices staged coalesced into lane regs, shfl-broadcast; gathered half2
// rows pairwise-added in fp16 (1 rounding), accumulated in fp32.
template <bool LAYER2>
__global__ void k_aggregate(const float* __restrict__ bias,
                            float* __restrict__ outp) {
    int gw   = (blockIdx.x * blockDim.x + threadIdx.x) >> 5;
    int lane = threadIdx.x & 31;
    if (gw >= N_NODES) return;

    const __half2* h2 = (const __half2*)(LAYER2 ? g_h2 : g_h1) + lane;
    float2*        o2 = LAYER2 ? (float2*)outp : (float2*)g_z1;

    float2 acc = __half22float2(h2[(size_t)gw * 32]);   // self term

    int e   = g_rowptr[gw];
    int end = g_rowptr[gw + 1];

    while (e < end) {
        int n = end - e;
        if (n > 32) n = 32;
        int idx = (lane < n) ? g_col[e + lane] : 0;     // coalesced batch load
        int j = 0;
        for (; j + 1 < n; j += 2) {
            int s0 = __shfl_sync(0xffffffffu, idx, j);
            int s1 = __shfl_sync(0xffffffffu, idx, j + 1);
            __half2 a = h2[(size_t)s0 * 32];
            __half2 b = h2[(size_t)s1 * 32];
            float2 f = __half22float2(__hadd2(a, b));   // 1 fp16 rounding
            acc.x += f.x;
            acc.y += f.y;
        }
        if (j < n) {
            int s0 = __shfl_sync(0xffffffffu, idx, j);
            float2 f = __half22float2(h2[(size_t)s0 * 32]);
            acc.x += f.x;
            acc.y += f.y;
        }
        e += n;
    }

    float  dvd = g_dinv[gw];
    float2 bb  = ((const float2*)bias)[lane];
    float ox = fmaf(acc.x, dvd, bb.x);
    float oy = fmaf(acc.y, dvd, bb.y);
    if (!LAYER2) { ox = fmaxf(ox, 0.0f); oy = fmaxf(oy, 0.0f); }
    o2[(size_t)gw * 32 + lane] = make_float2(ox, oy);
}

// ---------------- GEMM2 standalone -----------------------------------------
__global__ void k_gemm2(const float* __restrict__ W2) {
    __shared__ float At[32][132];
    __shared__ float Ws[32][68];
    gemm_body<HID_C>(g_z1, W2, g_h2, At, Ws, blockIdx.x * 128);
}

// ---------------- launch ---------------------------------------------------
extern "C" void kernel_launch(void* const* d_in, const int* in_sizes, int n_in,
                              void* d_out, int out_size) {
    const float* x  = (const float*)d_in[0];
    const void*  ei = d_in[1];                 // int32 OR int64 [2, 800000]
    const float* W1 = (const float*)d_in[2];
    const float* b1 = (const float*)d_in[3];
    const float* W2 = (const float*)d_in[4];
    const float* b2 = (const float*)d_in[5];
    float*      out = (float*)d_out;

    const int TB = 256;
    const int aggBlocks = (N_NODES * 32 + TB - 1) / TB;   // 6250

    k_convert_count<<<EDGE_BLKS, TB>>>(ei);               // edges -> g_src/g_dst/g_cnt
    k_scan<<<SCAN_BLKS, TB>>>();                          // rowptr + dinv
    k3_fused<<<GEMM_BLKS + EDGE_BLKS, TB>>>(x, W1);       // GEMM1*dinv || CSR fill
    k_aggregate<false><<<aggBlocks, TB>>>(b1, nullptr);   // -> g_z1 (ReLU)
    k_gemm2<<<GEMM_BLKS, TB>>>(W2);                       // -> g_h2 (dinv-scaled)
    k_aggregate<true><<<aggBlocks, TB>>>(b2, out);        // -> out
}

// round 8
// speedup vs baseline: 2.0648x; 1.0222x over previous
#include <cuda_runtime.h>
#include <cuda_fp16.h>

#define N_NODES 50000
#define N_EDGES 800000
#define IN_C    128
#define HID_C   64
#define OUT_C   64
#define GEMM_BLKS 391    // ceil(50000/128)
#define EDGE_BLKS 3125   // ceil(800000/256)
#define SCAN_BLKS 196    // ceil(50000/256)

// ---------------- scratch (static device globals; no allocations) ----------
// g_cnt: starts 0 (static init), CSR fill drains it back to 0 every run.
// g_bsum: reset to 0 inside k_convert_count every run.
__device__ int g_src[N_EDGES];
__device__ int g_dst[N_EDGES];
__device__ int g_cnt[N_NODES];
__device__ int g_bsum[SCAN_BLKS];
__device__ int g_rowptr[N_NODES + 1];
__device__ int g_col[N_EDGES];
__device__ __align__(16) float  g_dinv[N_NODES];
__device__ __align__(16) __half g_h1[N_NODES * HID_C];   // layer-1 h*dinv, fp16
__device__ __align__(16) float  g_z1[N_NODES * HID_C];   // layer-1 output, fp32
__device__ __align__(16) __half g_h2[N_NODES * OUT_C];   // layer-2 h*dinv, fp16

// ---------------- packed f32x2 helpers (Blackwell FFMA2) -------------------
#define FMA2(d, a, b, c) \
    asm("fma.rn.f32x2 %0, %1, %2, %3;" : "=l"(d) : "l"(a), "l"(b), "l"(c))
#define PACK2(d, f) \
    asm("mov.b64 %0, {%1, %1};" : "=l"(d) : "r"(__float_as_uint(f)))
#define UNPACK2(lo, hi, p) \
    asm("mov.b64 {%0, %1}, %2;" : "=f"(lo), "=f"(hi) : "l"(p))

static __device__ __forceinline__ unsigned packh(float a, float b) {
    __half2 h = __floats2half2_rn(a, b);
    return *reinterpret_cast<unsigned*>(&h);
}

// ---------------- GEMM body: 128x64 tile, K-chunk 32, FFMA2 ---------------
// outh[r][c] = dinv[r] * sum_k A[r][k] W[k][c], stored fp16
template <int K>
__device__ __forceinline__ void gemm_body(const float* __restrict__ A,
                                          const float* __restrict__ W,
                                          __half* __restrict__ outh,
                                          float At[32][132], float Ws[32][68],
                                          int row0) {
    const int tid = threadIdx.x;
    const int tx  = tid & 15;       // 4 cols:  tx*4 .. tx*4+3
    const int ty  = tid >> 4;       // 8 rows:  ty*8 .. ty*8+7 (4 row-pairs)

    unsigned long long acc[4][4];
    #pragma unroll
    for (int p = 0; p < 4; p++)
        #pragma unroll
        for (int c = 0; c < 4; c++) acc[p][c] = 0ULL;

    for (int kc = 0; kc < K; kc += 32) {
        if (kc) __syncthreads();
        #pragma unroll
        for (int l = 0; l < 2; l++) {                   // Ws: 32x64
            int j  = tid + l * 256;
            int k  = j >> 4;
            int c4 = (j & 15) << 2;
            *(float4*)&Ws[k][c4] = *(const float4*)(W + (size_t)(kc + k) * 64 + c4);
        }
        #pragma unroll
        for (int l = 0; l < 4; l++) {                   // At: transposed 128x32
            int j  = tid + l * 256;
            int r  = j >> 3;
            int k4 = (j & 7) << 2;
            float4 v = make_float4(0.f, 0.f, 0.f, 0.f);
            int row = row0 + r;
            if (row < N_NODES)
                v = *(const float4*)(A + (size_t)row * K + kc + k4);
            At[k4 + 0][r] = v.x;
            At[k4 + 1][r] = v.y;
            At[k4 + 2][r] = v.z;
            At[k4 + 3][r] = v.w;
        }
        __syncthreads();

        #pragma unroll 8
        for (int k = 0; k < 32; k++) {
            ulonglong2 a01 = *(const ulonglong2*)&At[k][ty * 8];
            ulonglong2 a23 = *(const ulonglong2*)&At[k][ty * 8 + 4];
            float4 b = *(const float4*)&Ws[k][tx * 4];
            unsigned long long B0, B1, B2, B3;
            PACK2(B0, b.x); PACK2(B1, b.y); PACK2(B2, b.z); PACK2(B3, b.w);
            FMA2(acc[0][0], a01.x, B0, acc[0][0]);
            FMA2(acc[0][1], a01.x, B1, acc[0][1]);
            FMA2(acc[0][2], a01.x, B2, acc[0][2]);
            FMA2(acc[0][3], a01.x, B3, acc[0][3]);
            FMA2(acc[1][0], a01.y, B0, acc[1][0]);
            FMA2(acc[1][1], a01.y, B1, acc[1][1]);
            FMA2(acc[1][2], a01.y, B2, acc[1][2]);
            FMA2(acc[1][3], a01.y, B3, acc[1][3]);
            FMA2(acc[2][0], a23.x, B0, acc[2][0]);
            FMA2(acc[2][1], a23.x, B1, acc[2][1]);
            FMA2(acc[2][2], a23.x, B2, acc[2][2]);
            FMA2(acc[2][3], a23.x, B3, acc[2][3]);
            FMA2(acc[3][0], a23.y, B0, acc[3][0]);
            FMA2(acc[3][1], a23.y, B1, acc[3][1]);
            FMA2(acc[3][2], a23.y, B2, acc[3][2]);
            FMA2(acc[3][3], a23.y, B3, acc[3][3]);
        }
    }

    #pragma unroll
    for (int p = 0; p < 4; p++) {
        float lo0, hi0, lo1, hi1, lo2, hi2, lo3, hi3;
        UNPACK2(lo0, hi0, acc[p][0]);
        UNPACK2(lo1, hi1, acc[p][1]);
        UNPACK2(lo2, hi2, acc[p][2]);
        UNPACK2(lo3, hi3, acc[p][3]);
        int r0 = row0 + ty * 8 + p * 2;
        if (r0 < N_NODES) {
            float s = g_dinv[r0];
            *(uint2*)(outh + (size_t)r0 * 64 + tx * 4) =
                make_uint2(packh(lo0 * s, lo1 * s), packh(lo2 * s, lo3 * s));
        }
        if (r0 + 1 < N_NODES) {
            float s = g_dinv[r0 + 1];
            *(uint2*)(outh + (size_t)(r0 + 1) * 64 + tx * 4) =
                make_uint2(packh(hi0 * s, hi1 * s), packh(hi2 * s, hi3 * s));
        }
    }
}

// ---------------- K1: convert + degree count (+ scan-flag reset) -----------
__global__ void k_convert_count(const void* __restrict__ ei) {
    __shared__ int s_nz;
    const int tid = threadIdx.x;
    if (tid == 0) s_nz = 0;
    __syncthreads();
    // dtype detection: int64 ids < 2^31 -> all odd 32-bit words zero
    if (tid < 128 && ((const int*)ei)[2 * tid + 1] != 0) atomicAdd(&s_nz, 1);
    __syncthreads();
    const bool is64 = (s_nz == 0);
    if (blockIdx.x == 0 && tid < SCAN_BLKS) g_bsum[tid] = 0;
    int i = blockIdx.x * 256 + tid;
    if (i < N_EDGES) {
        int s, d;
        if (is64) {
            const long long* e = (const long long*)ei;
            s = (int)e[i];
            d = (int)e[N_EDGES + i];
        } else {
            const int* e = (const int*)ei;
            s = e[i];
            d = e[N_EDGES + i];
        }
        if ((unsigned)s >= N_NODES) s = 0;   // defensive
        if ((unsigned)d >= N_NODES) d = 0;
        g_src[i] = s;
        g_dst[i] = d;
        atomicAdd(&g_cnt[d], 1);
    }
}

// ---------------- K2: single-kernel decoupled-lookback scan ----------------
__global__ void k_scan() {
    const int b = blockIdx.x, tid = threadIdx.x;
    const int i = b * 256 + tid;
    int v = (i < N_NODES) ? g_cnt[i] : 0;
    const int lane = tid & 31, w = tid >> 5;
    __shared__ int wsum[8];
    __shared__ int s_total, s_prefix;

    int s = v;
    #pragma unroll
    for (int off = 1; off < 32; off <<= 1) {
        int n = __shfl_up_sync(0xffffffffu, s, off);
        if (lane >= off) s += n;
    }
    if (lane == 31) wsum[w] = s;
    __syncthreads();
    if (tid == 0) {
        int acc = 0;
        #pragma unroll
        for (int j = 0; j < 8; j++) { int t = wsum[j]; wsum[j] = acc; acc += t; }
        s_total = acc;
    }
    __syncthreads();
    int incl = wsum[w] + s;               // block-local inclusive prefix

    if (tid == 0) atomicExch(&g_bsum[b], s_total + 1);   // publish (self-flag)
    if (tid < 32) {                        // lookback over predecessors
        int part = 0;
        for (int j = tid; j < b; j += 32) {
            int val;
            do { val = *(volatile int*)&g_bsum[j]; } while (val == 0);
            part += val - 1;
        }
        #pragma unroll
        for (int off = 16; off; off >>= 1)
            part += __shfl_down_sync(0xffffffffu, part, off);
        if (tid == 0) s_prefix = part;
    }
    __syncthreads();

    if (i < N_NODES) {
        g_rowptr[i + 1] = s_prefix + incl;
        g_dinv[i] = rsqrtf((float)(v + 1));   // +1 self loop
    }
    if (i == 0) g_rowptr[0] = 0;
}

// ---------------- K3: fused [GEMM1(*dinv) | CSR fill] ----------------------
__global__ void k3_fused(const float* __restrict__ x,
                         const float* __restrict__ W1) {
    if (blockIdx.x < GEMM_BLKS) {
        __shared__ float At[32][132];
        __shared__ float Ws[32][68];
        gemm_body<IN_C>(x, W1, g_h1, At, Ws, blockIdx.x * 128);
    } else {
        int i = (blockIdx.x - GEMM_BLKS) * 256 + threadIdx.x;
        if (i < N_EDGES) {
            int d = g_dst[i];
            int r = atomicSub(&g_cnt[d], 1);   // drains g_cnt back to 0
            int pos = g_rowptr[d] + r - 1;
            if ((unsigned)pos < N_EDGES) g_col[pos] = g_src[i];
        }
    }
}

// ---------------- aggregation: one warp per destination node ---------------
// hs holds h*dinv (pre-scaled); out[d] = dinv[d] * (hs[d] + sum hs[col]) + b
// MLP-8 restructure: 8 independent gathers issued back-to-back per iteration
// so each warp keeps 8 LDGs in flight against L2 latency.
template <bool LAYER2>
__global__ void k_aggregate(const float* __restrict__ bias,
                            float* __restrict__ outp) {
    int gw   = (blockIdx.x * blockDim.x + threadIdx.x) >> 5;
    int lane = threadIdx.x & 31;
    if (gw >= N_NODES) return;

    const __half2* h2 = (const __half2*)(LAYER2 ? g_h2 : g_h1) + lane;
    float2*        o2 = LAYER2 ? (float2*)outp : (float2*)g_z1;

    float2 acc = __half22float2(h2[(size_t)gw * 32]);   // self term

    int e   = g_rowptr[gw];
    int end = g_rowptr[gw + 1];

    while (e < end) {
        int n = end - e;
        if (n > 32) n = 32;
        int idx = (lane < n) ? g_col[e + lane] : 0;     // coalesced batch load
        int j = 0;
        for (; j + 8 <= n; j += 8) {
            int s0 = __shfl_sync(0xffffffffu, idx, j + 0);
            int s1 = __shfl_sync(0xffffffffu, idx, j + 1);
            int s2 = __shfl_sync(0xffffffffu, idx, j + 2);
            int s3 = __shfl_sync(0xffffffffu, idx, j + 3);
            int s4 = __shfl_sync(0xffffffffu, idx, j + 4);
            int s5 = __shfl_sync(0xffffffffu, idx, j + 5);
            int s6 = __shfl_sync(0xffffffffu, idx, j + 6);
            int s7 = __shfl_sync(0xffffffffu, idx, j + 7);
            __half2 a0 = h2[(size_t)s0 * 32];           // 8 independent LDGs
            __half2 a1 = h2[(size_t)s1 * 32];
            __half2 a2 = h2[(size_t)s2 * 32];
            __half2 a3 = h2[(size_t)s3 * 32];
            __half2 a4 = h2[(size_t)s4 * 32];
            __half2 a5 = h2[(size_t)s5 * 32];
            __half2 a6 = h2[(size_t)s6 * 32];
            __half2 a7 = h2[(size_t)s7 * 32];
            float2 f0 = __half22float2(__hadd2(a0, a1));
            float2 f1 = __half22float2(__hadd2(a2, a3));
            float2 f2 = __half22float2(__hadd2(a4, a5));
            float2 f3 = __half22float2(__hadd2(a6, a7));
            acc.x += (f0.x + f1.x) + (f2.x + f3.x);
            acc.y += (f0.y + f1.y) + (f2.y + f3.y);
        }
        for (; j + 2 <= n; j += 2) {
            int s0 = __shfl_sync(0xffffffffu, idx, j);
            int s1 = __shfl_sync(0xffffffffu, idx, j + 1);
            __half2 a = h2[(size_t)s0 * 32];
            __half2 b = h2[(size_t)s1 * 32];
            float2 f = __half22float2(__hadd2(a, b));
            acc.x += f.x;
            acc.y += f.y;
        }
        if (j < n) {
            int s0 = __shfl_sync(0xffffffffu, idx, j);
            float2 f = __half22float2(h2[(size_t)s0 * 32]);
            acc.x += f.x;
            acc.y += f.y;
        }
        e += n;
    }

    float  dvd = g_dinv[gw];
    float2 bb  = ((const float2*)bias)[lane];
    float ox = fmaf(acc.x, dvd, bb.x);
    float oy = fmaf(acc.y, dvd, bb.y);
    if (!LAYER2) { ox = fmaxf(ox, 0.0f); oy = fmaxf(oy, 0.0f); }
    o2[(size_t)gw * 32 + lane] = make_float2(ox, oy);
}

// ---------------- GEMM2 standalone -----------------------------------------
__global__ void k_gemm2(const float* __restrict__ W2) {
    __shared__ float At[32][132];
    __shared__ float Ws[32][68];
    gemm_body<HID_C>(g_z1, W2, g_h2, At, Ws, blockIdx.x * 128);
}

// ---------------- launch ---------------------------------------------------
extern "C" void kernel_launch(void* const* d_in, const int* in_sizes, int n_in,
                              void* d_out, int out_size) {
    const float* x  = (const float*)d_in[0];
    const void*  ei = d_in[1];                 // int32 OR int64 [2, 800000]
    const float* W1 = (const float*)d_in[2];
    const float* b1 = (const float*)d_in[3];
    const float* W2 = (const float*)d_in[4];
    const float* b2 = (const float*)d_in[5];
    float*      out = (float*)d_out;

    const int TB = 256;
    const int aggBlocks = (N_NODES * 32 + TB - 1) / TB;   // 6250

    k_convert_count<<<EDGE_BLKS, TB>>>(ei);               // edges -> g_src/g_dst/g_cnt
    k_scan<<<SCAN_BLKS, TB>>>();                          // rowptr + dinv
    k3_fused<<<GEMM_BLKS + EDGE_BLKS, TB>>>(x, W1);       // GEMM1*dinv || CSR fill
    k_aggregate<false><<<aggBlocks, TB>>>(b1, nullptr);   // -> g_z1 (ReLU)
    k_gemm2<<<GEMM_BLKS, TB>>>(W2);                       // -> g_h2 (dinv-scaled)
    k_aggregate<true><<<aggBlocks, TB>>>(b2, out);        // -> out
}